// round 9
// baseline (speedup 1.0000x reference)
#include <cuda_runtime.h>
#include <cuda_bf16.h>
#include <math.h>
#include <stdint.h>

// ---------------------------------------------------------------------------
// Problem constants
// ---------------------------------------------------------------------------
#define TT        256
#define BB        128
#define TB        32768            // T*B
#define OBS_DIM   1604
#define SCALAR_D  452
#define HID       128
#define NACT      2305
#define CNN_FLAT  2560
#define CHUNK     4096
#define NCHUNK    8

// d_out layout (elements): logits | values | h_f | c_f
#define OUT_LOGITS 0L
#define OUT_VALUES 75530240L
#define OUT_HF     75563008L
#define OUT_CF     75579392L

// Scratch pool offsets (floats) — static
#define S_SC1     0L              // 32768 x 64
#define S_EMB     2097152L        // 32768 x 192
#define S_XW      8388608L        // 32768 x 512
#define S_OUTS    25165824L       // 32768 x 128
#define SCRATCH   29360128L       // ~117 MB

__device__ float g_sc[SCRATCH];
__device__ float g_c3[(long)CHUNK * CNN_FLAT];   // 4096 x 2560 (~42 MB)
__device__ float g_whh[512 * 128];               // normalized f32 w_hh
__device__ int   g_done[TB];
__device__ int   g_bf16;

// ---------------------------------------------------------------------------
// Clamped, dtype-dispatched input load
// ---------------------------------------------------------------------------
__device__ __forceinline__ float ldin(const void* p, long i, long n, int bf)
{
    if (n <= 0) return 0.f;
    if (i >= n) i = n - 1;
    if (i < 0) i = 0;
    return bf ? __bfloat162float(((const __nv_bfloat16*)p)[i])
              : ((const float*)p)[i];
}

// ---------------------------------------------------------------------------
// dtype sniffer (clamped scan)
// ---------------------------------------------------------------------------
__global__ void detect_kernel(const void* __restrict__ obs_raw, long obs_n)
{
    __shared__ int s_cnt;
    if (threadIdx.x == 0) s_cnt = 0;
    __syncthreads();
    long lim = obs_n / 2;
    if (lim > 4096) lim = 4096;
    const unsigned* w = (const unsigned*)obs_raw;
    int c = 0;
    for (long i = threadIdx.x; i < lim; i += blockDim.x) {
        unsigned b1 = (w[i] >> 8) & 0xFF;
        if (b1 >= 0x3A && b1 < 0x40) c++;
    }
    atomicAdd(&s_cnt, c);
    __syncthreads();
    if (threadIdx.x == 0) g_bf16 = (s_cnt > (int)(lim / 2)) ? 1 : 0;
}

// ---------------------------------------------------------------------------
// done_mask normalizer (clamped scan + clamped expansion)
// ---------------------------------------------------------------------------
__global__ void done_normalize_kernel(const void* __restrict__ raw, long done_n)
{
    __shared__ int s_ni, s_nf, s_nb;
    const unsigned* w = (const unsigned*)raw;
    int tid = threadIdx.x;
    if (tid == 0) { s_ni = 0; s_nf = 0; s_nb = 0; }
    __syncthreads();

    long scan = done_n / 4;
    if (scan > 8192) scan = 8192;
    int ni = 0, nf = 0, nb = 0;
    for (long i = tid; i < scan; i += blockDim.x) {
        unsigned v = w[i];
        if (v > 1u) ni = 1;
        if (v != 0u && v != 0x3F800000u) nf = 1;
        unsigned lo = v & 0xFFFFu, hi = v >> 16;
        if ((lo != 0u && lo != 0x3F80u) || (hi != 0u && hi != 0x3F80u)) nb = 1;
    }
    if (ni) atomicOr(&s_ni, 1);
    if (nf) atomicOr(&s_nf, 1);
    if (nb) atomicOr(&s_nb, 1);
    __syncthreads();

    long lim = done_n < TB ? done_n : TB;
    if (!s_ni) {
        const int* p = (const int*)raw;
        for (int i = tid; i < TB; i += blockDim.x)
            g_done[i] = (i < lim) ? (p[i] != 0) : 0;
    } else if (!s_nf) {
        const float* p = (const float*)raw;
        for (int i = tid; i < TB; i += blockDim.x)
            g_done[i] = (i < lim) ? (p[i] != 0.f) : 0;
    } else if (!s_nb) {
        const unsigned short* p = (const unsigned short*)raw;
        for (int i = tid; i < TB; i += blockDim.x)
            g_done[i] = (i < lim) ? (p[i] != 0) : 0;
    } else {
        const unsigned char* p = (const unsigned char*)raw;
        for (int i = tid; i < TB; i += blockDim.x)
            g_done[i] = (i < lim) ? (p[i] != 0) : 0;
    }
}

// ---------------------------------------------------------------------------
// w_hh normalizer: raw (f32/bf16) -> g_whh f32
// ---------------------------------------------------------------------------
__global__ void whh_convert_kernel(const void* __restrict__ whh, long whh_n)
{
    int bf = g_bf16;
    for (int i = blockIdx.x * blockDim.x + threadIdx.x; i < 512 * 128;
         i += gridDim.x * blockDim.x)
        g_whh[i] = ldin(whh, i, whh_n, bf);
}

// ---------------------------------------------------------------------------
// Output store: dtype-dispatched, clamped
// ---------------------------------------------------------------------------
__device__ __forceinline__ void store_out(void* out, long idx, long out_elems, float v)
{
    if (idx >= out_elems || idx < 0) return;
    if (g_bf16) ((__nv_bfloat16*)out)[idx] = __float2bfloat16(v);
    else        ((float*)out)[idx] = v;
}

// ---------------------------------------------------------------------------
// Fused CNN, VANILLA smem (<= 48 KB static). One block per sample.
// conv1 produced 8-ch slices into smem; conv2 accumulates in registers
// (acc[4][9] per thread); conv3 accumulates in registers (acc[2][5]) over
// 16 weight slices reading unpadded c2 from smem.
//
// Phase-1 smem (floats): IN 0(1428) | C1S 1428(5712) | W2 7140(4608)
//                        | W1 11748(144) | B 11892(64)   end 11956
// Phase-2 smem:          C2 0(9216) | W3 9216(2304) | B 11892(64)
// ---------------------------------------------------------------------------
#define CV_IN   0
#define CV_C1   1428
#define CV_W2   7140
#define CV_C2   0
#define CV_W3   9216
#define CV_W1   11748
#define CV_B    11892
#define CV_TOT  12160    // 48,640 B static

__global__ void __launch_bounds__(256) conv_fused_kernel(
    const void* __restrict__ obs, long obs_n,
    const void* __restrict__ w1, long w1_n,
    const void* __restrict__ b1, long b1_n,
    const void* __restrict__ w2, long w2_n,
    const void* __restrict__ b2, long b2_n,
    const void* __restrict__ w3, long w3_n,
    const void* __restrict__ b3, long b3_n,
    float* __restrict__ c3out, int base)
{
    __shared__ float sm[CV_TOT];

    const int s   = base + blockIdx.x;
    const int tid = threadIdx.x;
    const int bf  = g_bf16;

    // zero IN + C1S regions (padding borders)
    for (int i = tid; i < CV_W2; i += 256) sm[i] = 0.f;
    __syncthreads();

    // input 2x32x18 -> padded IN ; b2 -> B
    const long gbase = (long)s * OBS_DIM + SCALAR_D;
    for (int i = tid; i < 1152; i += 256) {
        int c = i / 576, r = i % 576;
        int y = r / 18, x = r % 18;
        sm[CV_IN + c * 714 + (y + 1) * 21 + (x + 1)] = ldin(obs, gbase + i, obs_n, bf);
    }
    if (tid < 64) sm[CV_B + tid] = ldin(b2, tid, b2_n, bf);
    __syncthreads();

    // conv2 accumulators in registers: thread = (ocg 0..15, y 0..15), 4 oc x 9 x
    const int ocg2 = tid >> 4;
    const int y2   = tid & 15;
    float acc2[4][9];
    #pragma unroll
    for (int i = 0; i < 4; i++) {
        float bz = sm[CV_B + ocg2 * 4 + i];
        #pragma unroll
        for (int x = 0; x < 9; x++) acc2[i][x] = bz;
    }

    // ---- conv1 (8 channels at a time) + conv2 partial accumulation ----
    for (int ib = 0; ib < 4; ib++) {
        // load w1 slice (8 oc x 2 ic x 9 = 144) and w2 slice (64 x 8 x 9 = 4608)
        for (int i = tid; i < 144; i += 256)
            sm[CV_W1 + i] = ldin(w1, (long)ib * 144 + i, w1_n, bf);
        for (int i = tid; i < 4608; i += 256) {
            int oc = i / 72, rest = i % 72;       // rest = icl*9 + k
            int icl = rest / 9, k = rest % 9;
            sm[CV_W2 + i] = ldin(w2, (long)oc * 288 + (ib * 8 + icl) * 9 + k, w2_n, bf);
        }
        __syncthreads();

        // conv1: 8 oc x 32 y tasks = 256 -> one per thread, 18 x-outputs
        {
            int ocl = tid >> 5, y = tid & 31;
            int oc_g = ib * 8 + ocl;
            float acc[18];
            float bz = ldin(b1, oc_g, b1_n, bf);
            #pragma unroll
            for (int x = 0; x < 18; x++) acc[x] = bz;
            #pragma unroll
            for (int ic = 0; ic < 2; ic++) {
                #pragma unroll
                for (int ky = 0; ky < 3; ky++) {
                    const float* ip = sm + CV_IN + ic * 714 + (y + ky) * 21;
                    float in[20];
                    #pragma unroll
                    for (int q = 0; q < 20; q++) in[q] = ip[q];
                    const float* wp = sm + CV_W1 + (ocl * 2 + ic) * 9 + ky * 3;
                    float w0 = wp[0], wA = wp[1], wB = wp[2];
                    #pragma unroll
                    for (int x = 0; x < 18; x++)
                        acc[x] += w0 * in[x] + wA * in[x + 1] + wB * in[x + 2];
                }
            }
            #pragma unroll
            for (int x = 0; x < 18; x++)
                sm[CV_C1 + ocl * 714 + (y + 1) * 21 + (x + 1)] = fmaxf(acc[x], 0.f);
        }
        __syncthreads();

        // conv2 partial: accumulate over this 8-ic slice
        #pragma unroll 1
        for (int icl = 0; icl < 8; icl++) {
            #pragma unroll
            for (int ky = 0; ky < 3; ky++) {
                const float* ip = sm + CV_C1 + icl * 714 + (2 * y2 + ky) * 21;
                float in[19];
                #pragma unroll
                for (int q = 0; q < 19; q++) in[q] = ip[q];
                #pragma unroll
                for (int i = 0; i < 4; i++) {
                    const float* wp = sm + CV_W2 + (ocg2 * 4 + i) * 72 + icl * 9 + ky * 3;
                    float w0 = wp[0], wA = wp[1], wB = wp[2];
                    #pragma unroll
                    for (int x = 0; x < 9; x++)
                        acc2[i][x] += w0 * in[2 * x] + wA * in[2 * x + 1] + wB * in[2 * x + 2];
                }
            }
        }
        __syncthreads();   // before overwriting C1S / W slices
    }

    // write c2 (ReLU, unpadded 64x16x9) + load b3
    #pragma unroll
    for (int i = 0; i < 4; i++)
        #pragma unroll
        for (int x = 0; x < 9; x++)
            sm[CV_C2 + (ocg2 * 4 + i) * 144 + y2 * 9 + x] = fmaxf(acc2[i][x], 0.f);
    if (tid < 64) sm[CV_B + tid] = ldin(b3, tid, b3_n, bf);
    __syncthreads();

    // ---- conv3: thread = (ocg 0..31, y 0..7), 2 oc x 5 x; 16 slices of 4 ic
    const int ocg3 = tid >> 3;
    const int y3   = tid & 7;
    float acc3[2][5];
    #pragma unroll
    for (int i = 0; i < 2; i++) {
        float bz = sm[CV_B + ocg3 * 2 + i];
        #pragma unroll
        for (int x = 0; x < 5; x++) acc3[i][x] = bz;
    }

    for (int ib = 0; ib < 16; ib++) {
        for (int i = tid; i < 2304; i += 256) {
            int oc = i / 36, rest = i % 36;       // rest = icl*9 + k
            int icl = rest / 9, k = rest % 9;
            sm[CV_W3 + i] = ldin(w3, (long)oc * 576 + (ib * 4 + icl) * 9 + k, w3_n, bf);
        }
        __syncthreads();

        #pragma unroll
        for (int icl = 0; icl < 4; icl++) {
            int ic = ib * 4 + icl;
            #pragma unroll
            for (int ky = 0; ky < 3; ky++) {
                int row = 2 * y3 + ky - 1;
                float in[11];
                if (row >= 0 && row < 16) {
                    const float* cp = sm + CV_C2 + ic * 144 + row * 9;
                    #pragma unroll
                    for (int q = 0; q < 11; q++)
                        in[q] = (q >= 1 && q <= 9) ? cp[q - 1] : 0.f;
                } else {
                    #pragma unroll
                    for (int q = 0; q < 11; q++) in[q] = 0.f;
                }
                #pragma unroll
                for (int i = 0; i < 2; i++) {
                    const float* wp = sm + CV_W3 + (ocg3 * 2 + i) * 36 + icl * 9 + ky * 3;
                    float w0 = wp[0], wA = wp[1], wB = wp[2];
                    #pragma unroll
                    for (int x = 0; x < 5; x++)
                        acc3[i][x] += w0 * in[2 * x] + wA * in[2 * x + 1] + wB * in[2 * x + 2];
                }
            }
        }
        __syncthreads();
    }

    float* outp = c3out + (long)blockIdx.x * CNN_FLAT;
    #pragma unroll
    for (int i = 0; i < 2; i++)
        #pragma unroll
        for (int x = 0; x < 5; x++)
            outp[(long)(ocg3 * 2 + i) * 40 + y3 * 5 + x] = fmaxf(acc3[i][x], 0.f);
}

// ---------------------------------------------------------------------------
// Generic tiled SGEMM (vanilla 8.7 KB static smem), clamped raw reads
// ---------------------------------------------------------------------------
template <bool RELU, bool TO_OUT>
__global__ void __launch_bounds__(256, 2) gemm_bt_kernel(
    const void* __restrict__ Araw, long a_n,
    const float* __restrict__ Af, long lda,
    const void* __restrict__ B, long b_n,
    const void* __restrict__ bias, long bias_n,
    const void* __restrict__ bias2, long bias2_n,
    float* __restrict__ Cf, long c_off, long ldc, int N, int K,
    void* outbuf, long out_elems)
{
    __shared__ float sA[16][68];
    __shared__ float sB[16][68];

    const int tid = threadIdx.x;
    const int tx = tid & 15, ty = tid >> 4;
    const int m0 = blockIdx.x * 64;
    const int n0 = blockIdx.y * 64;
    const int bf = g_bf16;

    float acc[4][4] = {};

    for (int k0 = 0; k0 < K; k0 += 16) {
        for (int e = tid; e < 1024; e += 256) {
            int k = e & 15, m = e >> 4;
            int gk = k0 + k;
            float v = 0.f;
            if (gk < K) {
                long ai = (long)(m0 + m) * lda + gk;
                v = Af ? Af[ai] : ldin(Araw, ai, a_n, bf);
            }
            sA[k][m] = v;
        }
        for (int e = tid; e < 1024; e += 256) {
            int k = e & 15, n = e >> 4;
            int gn = n0 + n, gk = k0 + k;
            sB[k][n] = (gn < N && gk < K) ? ldin(B, (long)gn * K + gk, b_n, bf) : 0.f;
        }
        __syncthreads();
        #pragma unroll
        for (int kk = 0; kk < 16; kk++) {
            float4 av = *(const float4*)&sA[kk][ty * 4];
            float4 bv = *(const float4*)&sB[kk][tx * 4];
            float a[4] = {av.x, av.y, av.z, av.w};
            float b[4] = {bv.x, bv.y, bv.z, bv.w};
            #pragma unroll
            for (int i = 0; i < 4; i++)
                #pragma unroll
                for (int j = 0; j < 4; j++)
                    acc[i][j] += a[i] * b[j];
        }
        __syncthreads();
    }

    #pragma unroll
    for (int i = 0; i < 4; i++) {
        int gm = m0 + ty * 4 + i;
        #pragma unroll
        for (int j = 0; j < 4; j++) {
            int gn = n0 + tx * 4 + j;
            if (gn < N) {
                float v = acc[i][j];
                if (bias)  v += ldin(bias,  gn, bias_n,  bf);
                if (bias2) v += ldin(bias2, gn, bias2_n, bf);
                if (RELU) v = fmaxf(v, 0.f);
                if (TO_OUT) store_out(outbuf, c_off + (long)gm * ldc + gn, out_elems, v);
                else        Cf[(long)gm * ldc + gn] = v;
            }
        }
    }
}

// ---------------------------------------------------------------------------
// LSTM, VANILLA smem (<= 47.6 KB static). One CTA per batch element.
// w_hh row r: cols 0..63 in registers, cols 64..85 in transposed smem
// (conflict-free), cols 86..127 from g_whh (L1-resident after step 1).
// ---------------------------------------------------------------------------
#define LW_SM_W2   0        // 22 * 512 transposed
#define LW_SM_H    11264    // 128
#define LW_SM_G    11392    // 512
#define LW_SM_TOT  11904    // 47,616 B static

__global__ void __launch_bounds__(512) lstm_kernel(
    const void* __restrict__ h0, long h0_n,
    const void* __restrict__ c0, long c0_n,
    void* outbuf, long out_elems)
{
    __shared__ float sm[LW_SM_TOT];
    float* s_w2t = sm + LW_SM_W2;
    float* s_h   = sm + LW_SM_H;
    float* s_g   = sm + LW_SM_G;

    const int b = blockIdx.x;
    const int r = threadIdx.x;
    const int bf = g_bf16;

    const float* xw   = g_sc + S_XW;
    float*       outs = g_sc + S_OUTS;

    float wreg[64];
    #pragma unroll
    for (int k = 0; k < 64; k++) wreg[k] = g_whh[r * 128 + k];
    #pragma unroll
    for (int k = 0; k < 22; k++) s_w2t[k * 512 + r] = g_whh[r * 128 + 64 + k];

    float c = 0.f;
    if (r < 128) {
        s_h[r] = ldin(h0, (long)b * 128 + r, h0_n, bf);
        c      = ldin(c0, (long)b * 128 + r, c0_n, bf);
    }
    __syncthreads();

    for (int t = 0; t < TT; t++) {
        if (r < 128) {
            float keep = (t == 0) ? 1.f : (g_done[(t - 1) * BB + b] ? 0.f : 1.f);
            s_h[r] *= keep;
            c *= keep;
        }
        __syncthreads();

        float acc = xw[((long)t * BB + b) * 512 + r];
        #pragma unroll
        for (int k = 0; k < 64; k += 4) {
            float4 h4 = *(const float4*)&s_h[k];
            acc += wreg[k] * h4.x + wreg[k + 1] * h4.y
                 + wreg[k + 2] * h4.z + wreg[k + 3] * h4.w;
        }
        #pragma unroll
        for (int k = 0; k < 22; k++)
            acc += s_w2t[k * 512 + r] * s_h[64 + k];
        const float* wg = g_whh + r * 128 + 86;
        #pragma unroll
        for (int k = 0; k < 42; k++)
            acc += wg[k] * s_h[86 + k];
        s_g[r] = acc;
        __syncthreads();

        if (r < 128) {
            float ig = 1.f / (1.f + expf(-s_g[r]));
            float fg = 1.f / (1.f + expf(-s_g[128 + r]));
            float gg = tanhf(s_g[256 + r]);
            float og = 1.f / (1.f + expf(-s_g[384 + r]));
            c = fg * c + ig * gg;
            float h = og * tanhf(c);
            s_h[r] = h;
            outs[((long)t * BB + b) * 128 + r] = h;
        }
        __syncthreads();
    }

    if (r < 128) {
        store_out(outbuf, OUT_HF + (long)b * 128 + r, out_elems, s_h[r]);
        store_out(outbuf, OUT_CF + (long)b * 128 + r, out_elems, c);
    }
}

// ---------------------------------------------------------------------------
// Value head: one warp per sample
// ---------------------------------------------------------------------------
__global__ void value_kernel(const void* __restrict__ vw, long vw_n,
                             const void* __restrict__ vb, long vb_n,
                             void* outbuf, long out_elems)
{
    int gw   = (blockIdx.x * blockDim.x + threadIdx.x) >> 5;
    int lane = threadIdx.x & 31;
    if (gw >= TB) return;
    const int bf = g_bf16;
    const float* h = g_sc + S_OUTS + (long)gw * 128;
    float s = 0.f;
    #pragma unroll
    for (int k = lane; k < 128; k += 32) s += h[k] * ldin(vw, k, vw_n, bf);
    #pragma unroll
    for (int off = 16; off; off >>= 1) s += __shfl_xor_sync(0xffffffffu, s, off);
    if (lane == 0)
        store_out(outbuf, OUT_VALUES + gw, out_elems, s + ldin(vb, 0, vb_n, bf));
}

// ---------------------------------------------------------------------------
// Host launcher — NO cudaFuncSetAttribute, NO dynamic smem anywhere.
// ---------------------------------------------------------------------------
extern "C" void kernel_launch(void* const* d_in, const int* in_sizes, int n_in,
                              void* d_out, int out_size)
{
    static const long WANT[24] = {
        52559872L, 16384L, 16384L, 32768L,
        576L, 32L, 18432L, 64L, 36864L, 64L,
        327680L, 128L, 28928L, 64L, 4096L, 64L,
        98304L, 65536L, 512L, 512L,
        295040L, 2305L, 128L, 1L
    };
    const void* inp[24];
    long        bnd[24];
    {
        int matched = 0;
        static const long SCALES[3] = {1L, 4L, 2L};
        for (int si = 0; si < 3 && !matched; si++) {
            long sc = SCALES[si];
            int used[64] = {0};
            int ok = (n_in >= 24);
            const void* tp[24]; long tb[24];
            if (ok) {
                for (int j = 0; j < 24; j++) {
                    int found = -1;
                    for (int i = 0; i < n_in && i < 64; i++) {
                        if (!used[i] && (long)in_sizes[i] == WANT[j] * sc) { found = i; break; }
                    }
                    if (found < 0) { ok = 0; break; }
                    used[found] = 1;
                    tp[j] = d_in[found];
                    long actual = (long)in_sizes[found];
                    tb[j] = (WANT[j] < actual) ? WANT[j] : actual;
                }
            }
            if (ok) {
                for (int j = 0; j < 24; j++) { inp[j] = tp[j]; bnd[j] = tb[j]; }
                matched = 1;
            }
        }
        if (!matched) {
            for (int j = 0; j < 24; j++) {
                if (j < n_in) {
                    inp[j] = d_in[j];
                    long actual = (long)in_sizes[j];
                    bnd[j] = (WANT[j] < actual) ? WANT[j] : actual;
                } else {
                    inp[j] = d_in[0];
                    bnd[j] = 0;
                }
            }
        }
    }

    const long out_elems = (long)out_size;

    float *scP, *c3P;
    cudaGetSymbolAddress((void**)&scP, g_sc);
    cudaGetSymbolAddress((void**)&c3P, g_c3);

    // 1) dtype sniff + normalizers
    detect_kernel<<<1, 256>>>(inp[0], bnd[0]);
    done_normalize_kernel<<<1, 1024>>>(inp[3], bnd[3]);
    whh_convert_kernel<<<64, 256>>>(inp[17], bnd[17]);

    // 2) chunked CNN + fc GEMM -> emb cols 0..127
    for (int ch = 0; ch < NCHUNK; ch++) {
        int base = ch * CHUNK;
        conv_fused_kernel<<<CHUNK, 256>>>(
            inp[0], bnd[0], inp[4], bnd[4], inp[5], bnd[5],
            inp[6], bnd[6], inp[7], bnd[7], inp[8], bnd[8], inp[9], bnd[9],
            c3P, base);
        gemm_bt_kernel<true, false><<<dim3(CHUNK / 64, 2), 256>>>(
            nullptr, 0L, c3P, CNN_FLAT,
            inp[10], bnd[10], inp[11], bnd[11], nullptr, 0L,
            scP + S_EMB + (long)base * 192, 0L, 192, 128, CNN_FLAT,
            d_out, out_elems);
    }

    // 3) Scalar MLP -> emb cols 128..191
    gemm_bt_kernel<true, false><<<dim3(TB / 64, 1), 256>>>(
        inp[0], bnd[0], nullptr, OBS_DIM,
        inp[12], bnd[12], inp[13], bnd[13], nullptr, 0L,
        scP + S_SC1, 0L, 64, 64, SCALAR_D, d_out, out_elems);
    gemm_bt_kernel<true, false><<<dim3(TB / 64, 1), 256>>>(
        nullptr, 0L, scP + S_SC1, 64,
        inp[14], bnd[14], inp[15], bnd[15], nullptr, 0L,
        scP + S_EMB + 128, 0L, 192, 64, 64, d_out, out_elems);

    // 4) LSTM input projection
    gemm_bt_kernel<false, false><<<dim3(TB / 64, 8), 256>>>(
        nullptr, 0L, scP + S_EMB, 192,
        inp[16], bnd[16], inp[18], bnd[18], inp[19], bnd[19],
        scP + S_XW, 0L, 512, 512, 192, d_out, out_elems);

    // 5) Recurrence
    lstm_kernel<<<BB, 512>>>(inp[1], bnd[1], inp[2], bnd[2], d_out, out_elems);

    // 6) Policy head -> logits
    gemm_bt_kernel<false, true><<<dim3(TB / 64, (NACT + 63) / 64), 256>>>(
        nullptr, 0L, scP + S_OUTS, 128,
        inp[20], bnd[20], inp[21], bnd[21], nullptr, 0L,
        nullptr, OUT_LOGITS, NACT, NACT, 128, d_out, out_elems);

    // 7) Value head -> values
    value_kernel<<<TB / 8, 256>>>(inp[22], bnd[22], inp[23], bnd[23],
                                  d_out, out_elems);
}

// round 11
// speedup vs baseline: 1.1258x; 1.1258x over previous
#include <cuda_runtime.h>
#include <cuda_bf16.h>
#include <math.h>
#include <stdint.h>

typedef unsigned long long ull;

// ---------------------------------------------------------------------------
// Problem constants
// ---------------------------------------------------------------------------
#define TT        256
#define BB        128
#define TB        32768            // T*B
#define OBS_DIM   1604
#define SCALAR_D  452
#define HID       128
#define NACT      2305
#define CNN_FLAT  2560
#define CHUNK     4096
#define NCHUNK    8

// d_out layout (elements): logits | values | h_f | c_f
#define OUT_LOGITS 0L
#define OUT_VALUES 75530240L
#define OUT_HF     75563008L
#define OUT_CF     75579392L

// Scratch pool offsets (floats) — static
#define S_SC1     0L              // 32768 x 64
#define S_EMB     2097152L        // 32768 x 192
#define S_XW      8388608L        // 32768 x 512
#define S_OUTS    25165824L       // 32768 x 128
#define SCRATCH   29360128L       // ~117 MB

__device__ float g_sc[SCRATCH];
__device__ float g_c3[(long)CHUNK * CNN_FLAT];   // 4096 x 2560 (~42 MB)
__device__ float g_whh[512 * 128];               // normalized f32 w_hh
__device__ int   g_done[TB];
__device__ int   g_bf16;

// Prepped conv weights (f32, pair-interleaved for f32x2)
__device__ float g_w1[576];
__device__ float g_b1[32];
__device__ float g_b2[64];
__device__ float g_b3[64];
__device__ float g_w2p[18432];   // (ib4, pr32, icl8, ky3, k3, o2)
__device__ float g_w3p[36864];   // (ib32, pr32, icl2, ky3, k3, o2)

// ---------------------------------------------------------------------------
// f32x2 packed-math helpers (sm_100a PTX)
// ---------------------------------------------------------------------------
__device__ __forceinline__ ull bc2(float v)
{ ull r; asm("mov.b64 %0, {%1, %1};" : "=l"(r) : "f"(v)); return r; }
__device__ __forceinline__ ull pk2(float a, float b)
{ ull r; asm("mov.b64 %0, {%1, %2};" : "=l"(r) : "f"(a), "f"(b)); return r; }
__device__ __forceinline__ float2 up2(ull v)
{ float2 f; asm("mov.b64 {%0, %1}, %2;" : "=f"(f.x), "=f"(f.y) : "l"(v)); return f; }
__device__ __forceinline__ void fma2(ull& d, ull a, ull b)
{ asm("fma.rn.f32x2 %0, %1, %2, %0;" : "+l"(d) : "l"(a), "l"(b)); }

// ---------------------------------------------------------------------------
// Clamped, dtype-dispatched input load
// ---------------------------------------------------------------------------
__device__ __forceinline__ float ldin(const void* p, long i, long n, int bf)
{
    if (n <= 0) return 0.f;
    if (i >= n) i = n - 1;
    if (i < 0) i = 0;
    return bf ? __bfloat162float(((const __nv_bfloat16*)p)[i])
              : ((const float*)p)[i];
}

// ---------------------------------------------------------------------------
// dtype sniffer (clamped scan)
// ---------------------------------------------------------------------------
__global__ void detect_kernel(const void* __restrict__ obs_raw, long obs_n)
{
    __shared__ int s_cnt;
    if (threadIdx.x == 0) s_cnt = 0;
    __syncthreads();
    long lim = obs_n / 2;
    if (lim > 4096) lim = 4096;
    const unsigned* w = (const unsigned*)obs_raw;
    int c = 0;
    for (long i = threadIdx.x; i < lim; i += blockDim.x) {
        unsigned b1 = (w[i] >> 8) & 0xFF;
        if (b1 >= 0x3A && b1 < 0x40) c++;
    }
    atomicAdd(&s_cnt, c);
    __syncthreads();
    if (threadIdx.x == 0) g_bf16 = (s_cnt > (int)(lim / 2)) ? 1 : 0;
}

// ---------------------------------------------------------------------------
// done_mask normalizer (clamped scan + clamped expansion)
// ---------------------------------------------------------------------------
__global__ void done_normalize_kernel(const void* __restrict__ raw, long done_n)
{
    __shared__ int s_ni, s_nf, s_nb;
    const unsigned* w = (const unsigned*)raw;
    int tid = threadIdx.x;
    if (tid == 0) { s_ni = 0; s_nf = 0; s_nb = 0; }
    __syncthreads();

    long scan = done_n / 4;
    if (scan > 8192) scan = 8192;
    int ni = 0, nf = 0, nb = 0;
    for (long i = tid; i < scan; i += blockDim.x) {
        unsigned v = w[i];
        if (v > 1u) ni = 1;
        if (v != 0u && v != 0x3F800000u) nf = 1;
        unsigned lo = v & 0xFFFFu, hi = v >> 16;
        if ((lo != 0u && lo != 0x3F80u) || (hi != 0u && hi != 0x3F80u)) nb = 1;
    }
    if (ni) atomicOr(&s_ni, 1);
    if (nf) atomicOr(&s_nf, 1);
    if (nb) atomicOr(&s_nb, 1);
    __syncthreads();

    long lim = done_n < TB ? done_n : TB;
    if (!s_ni) {
        const int* p = (const int*)raw;
        for (int i = tid; i < TB; i += blockDim.x)
            g_done[i] = (i < lim) ? (p[i] != 0) : 0;
    } else if (!s_nf) {
        const float* p = (const float*)raw;
        for (int i = tid; i < TB; i += blockDim.x)
            g_done[i] = (i < lim) ? (p[i] != 0.f) : 0;
    } else if (!s_nb) {
        const unsigned short* p = (const unsigned short*)raw;
        for (int i = tid; i < TB; i += blockDim.x)
            g_done[i] = (i < lim) ? (p[i] != 0) : 0;
    } else {
        const unsigned char* p = (const unsigned char*)raw;
        for (int i = tid; i < TB; i += blockDim.x)
            g_done[i] = (i < lim) ? (p[i] != 0) : 0;
    }
}

// ---------------------------------------------------------------------------
// w_hh normalizer
// ---------------------------------------------------------------------------
__global__ void whh_convert_kernel(const void* __restrict__ whh, long whh_n)
{
    int bf = g_bf16;
    for (int i = blockIdx.x * blockDim.x + threadIdx.x; i < 512 * 128;
         i += gridDim.x * blockDim.x)
        g_whh[i] = ldin(whh, i, whh_n, bf);
}

// ---------------------------------------------------------------------------
// Conv-weight prep: convert to f32 and pair-interleave for f32x2 kernels.
// g_w2p[(ib,pr,icl,ky,k,o)]: oc = pr*2+o, ic = ib*8+icl
// g_w3p[(ib,pr,icl,ky,k,o)]: oc = pr*2+o, ic = ib*2+icl
// ---------------------------------------------------------------------------
__global__ void weights_prep_kernel(
    const void* __restrict__ w1, long n1, const void* __restrict__ b1, long nb1,
    const void* __restrict__ w2, long n2, const void* __restrict__ b2, long nb2,
    const void* __restrict__ w3, long n3, const void* __restrict__ b3, long nb3)
{
    int bf = g_bf16;
    int stride = gridDim.x * blockDim.x;
    for (int j = blockIdx.x * blockDim.x + threadIdx.x; j < 36864; j += stride) {
        {   // w3p
            int o = j & 1; int t = j >> 1;
            int k = t % 3; t /= 3;
            int ky = t % 3; t /= 3;
            int icl = t & 1; t >>= 1;
            int pr = t & 31; int ib = t >> 5;
            g_w3p[j] = ldin(w3, (long)(pr * 2 + o) * 576 + (ib * 2 + icl) * 9 + ky * 3 + k, n3, bf);
        }
        if (j < 18432) {   // w2p
            int o = j & 1; int t = j >> 1;
            int k = t % 3; t /= 3;
            int ky = t % 3; t /= 3;
            int icl = t & 7; t >>= 3;
            int pr = t & 31; int ib = t >> 5;
            g_w2p[j] = ldin(w2, (long)(pr * 2 + o) * 288 + (ib * 8 + icl) * 9 + ky * 3 + k, n2, bf);
        }
        if (j < 576) g_w1[j] = ldin(w1, j, n1, bf);
        if (j < 32)  g_b1[j] = ldin(b1, j, nb1, bf);
        if (j < 64) { g_b2[j] = ldin(b2, j, nb2, bf); g_b3[j] = ldin(b3, j, nb3, bf); }
    }
}

// ---------------------------------------------------------------------------
// Output store: dtype-dispatched, clamped
// ---------------------------------------------------------------------------
__device__ __forceinline__ void store_out(void* out, long idx, long out_elems, float v)
{
    if (idx >= out_elems || idx < 0) return;
    if (g_bf16) ((__nv_bfloat16*)out)[idx] = __float2bfloat16(v);
    else        ((float*)out)[idx] = v;
}

// ---------------------------------------------------------------------------
// Fused CNN with f32x2 packed math. Static smem 48,224 B. 1 block/sample.
// Phase1 (floats): IN @0 (2*34*22=1496) | C1 @1496 (8*33*22=5808)
//                  | W2 @7304 (4608) | W1 @11912 (144)    -> 12056 total
// Phase2:          C2 @0 (64*16*10=10240) | W3 @10240 (1152)
// ---------------------------------------------------------------------------
#define CV_IN   0
#define CV_C1   1496
#define CV_W2   7304
#define CV_W1   11912
#define CV_C2   0
#define CV_W3   10240
#define CV_TOT  12056

__global__ void __launch_bounds__(256) conv_fused_kernel(
    const void* __restrict__ obs, long obs_n,
    float* __restrict__ c3out, int base)
{
    __shared__ __align__(16) float sm[CV_TOT];

    const int tid = threadIdx.x;
    const int bf  = g_bf16;
    const int s   = base + blockIdx.x;

    // zero IN + C1 (padding borders persist across ib slices)
    for (int i = tid; i < CV_W2; i += 256) sm[i] = 0.f;
    __syncthreads();

    // obs grid -> padded IN
    const long gbase = (long)s * OBS_DIM + SCALAR_D;
    for (int i = tid; i < 1152; i += 256) {
        int c = i / 576, r = i % 576;
        int y = r / 18, x = r % 18;
        sm[CV_IN + c * 748 + (y + 1) * 22 + (x + 1)] = ldin(obs, gbase + i, obs_n, bf);
    }

    // conv2 accumulators: thread = (ocg2 0..15 -> 4 oc = 2 pairs, y2 0..15)
    const int ocg2 = tid >> 4, y2 = tid & 15;
    ull acc2p[2][9];
    #pragma unroll
    for (int p = 0; p < 2; p++) {
        ull bz = pk2(g_b2[ocg2 * 4 + 2 * p], g_b2[ocg2 * 4 + 2 * p + 1]);
        #pragma unroll
        for (int x = 0; x < 9; x++) acc2p[p][x] = bz;
    }
    const int ocl = tid >> 5, y1 = tid & 31;

    // ---- conv1 (8 oc slices) + conv2 partial ----
    for (int ib = 0; ib < 4; ib++) {
        for (int i = tid; i < 144; i += 256) sm[CV_W1 + i] = g_w1[ib * 144 + i];
        for (int i = tid; i < 1152; i += 256)
            ((float4*)(sm + CV_W2))[i] = ((const float4*)(g_w2p + ib * 4608))[i];
        __syncthreads();

        // conv1: one (ocl, y1) per thread, 18 x-outputs
        {
            float acc[18];
            float bz = g_b1[ib * 8 + ocl];
            #pragma unroll
            for (int x = 0; x < 18; x++) acc[x] = bz;
            #pragma unroll
            for (int ic = 0; ic < 2; ic++) {
                #pragma unroll
                for (int ky = 0; ky < 3; ky++) {
                    const float2* ip2 = (const float2*)(sm + CV_IN + ic * 748 + (y1 + ky) * 22);
                    float in[20];
                    #pragma unroll
                    for (int q = 0; q < 10; q++) {
                        float2 t = ip2[q]; in[2 * q] = t.x; in[2 * q + 1] = t.y;
                    }
                    const float* wp = sm + CV_W1 + (ocl * 2 + ic) * 9 + ky * 3;
                    float w0 = wp[0], wA = wp[1], wB = wp[2];
                    #pragma unroll
                    for (int x = 0; x < 18; x++)
                        acc[x] += w0 * in[x] + wA * in[x + 1] + wB * in[x + 2];
                }
            }
            #pragma unroll
            for (int x = 0; x < 18; x++)
                sm[CV_C1 + ocl * 726 + (y1 + 1) * 22 + (x + 1)] = fmaxf(acc[x], 0.f);
        }
        __syncthreads();

        // conv2 partial over this 8-ic slice (f32x2, oc pairs)
        #pragma unroll 1
        for (int icl = 0; icl < 8; icl++) {
            #pragma unroll
            for (int ky = 0; ky < 3; ky++) {
                const float2* ip2 = (const float2*)(sm + CV_C1 + icl * 726 + (2 * y2 + ky) * 22);
                float in[20];
                #pragma unroll
                for (int q = 0; q < 10; q++) {
                    float2 t = ip2[q]; in[2 * q] = t.x; in[2 * q + 1] = t.y;
                }
                const ull* wp = (const ull*)(sm + CV_W2);
                ull w[2][3];
                #pragma unroll
                for (int p = 0; p < 2; p++) {
                    int wb = (((ocg2 * 2 + p) * 8 + icl) * 3 + ky) * 3;
                    w[p][0] = wp[wb]; w[p][1] = wp[wb + 1]; w[p][2] = wp[wb + 2];
                }
                #pragma unroll
                for (int x = 0; x < 9; x++) {
                    ull b0 = bc2(in[2 * x]);
                    ull b1v = bc2(in[2 * x + 1]);
                    ull b2v = bc2(in[2 * x + 2]);
                    fma2(acc2p[0][x], w[0][0], b0);
                    fma2(acc2p[0][x], w[0][1], b1v);
                    fma2(acc2p[0][x], w[0][2], b2v);
                    fma2(acc2p[1][x], w[1][0], b0);
                    fma2(acc2p[1][x], w[1][1], b1v);
                    fma2(acc2p[1][x], w[1][2], b2v);
                }
            }
        }
        __syncthreads();
    }

    // write c2 (ReLU) to phase-2 region (pitch 10)
    #pragma unroll
    for (int p = 0; p < 2; p++)
        #pragma unroll
        for (int x = 0; x < 9; x++) {
            float2 f = up2(acc2p[p][x]);
            sm[CV_C2 + (ocg2 * 4 + 2 * p + 0) * 160 + y2 * 10 + x] = fmaxf(f.x, 0.f);
            sm[CV_C2 + (ocg2 * 4 + 2 * p + 1) * 160 + y2 * 10 + x] = fmaxf(f.y, 0.f);
        }
    __syncthreads();

    // ---- conv3: thread = (ocg3 0..31 -> 1 oc pair, y3 0..7), 32 ic slices ----
    const int ocg3 = tid >> 3, y3 = tid & 7;
    ull acc3p[5];
    {
        ull bz = pk2(g_b3[ocg3 * 2], g_b3[ocg3 * 2 + 1]);
        #pragma unroll
        for (int x = 0; x < 5; x++) acc3p[x] = bz;
    }

    for (int ib = 0; ib < 32; ib++) {
        for (int i = tid; i < 288; i += 256)
            ((float4*)(sm + CV_W3))[i] = ((const float4*)(g_w3p + ib * 1152))[i];
        __syncthreads();

        #pragma unroll
        for (int icl = 0; icl < 2; icl++) {
            int ic = ib * 2 + icl;
            #pragma unroll
            for (int ky = 0; ky < 3; ky++) {
                int row = 2 * y3 + ky - 1;
                float in[11];
                if (row >= 0 && row < 16) {
                    const float2* cp2 = (const float2*)(sm + CV_C2 + ic * 160 + row * 10);
                    float2 t0 = cp2[0], t1 = cp2[1], t2 = cp2[2], t3 = cp2[3], t4 = cp2[4];
                    in[0] = 0.f;
                    in[1] = t0.x; in[2] = t0.y; in[3] = t1.x; in[4] = t1.y;
                    in[5] = t2.x; in[6] = t2.y; in[7] = t3.x; in[8] = t3.y;
                    in[9] = t4.x; in[10] = 0.f;
                } else {
                    #pragma unroll
                    for (int q = 0; q < 11; q++) in[q] = 0.f;
                }
                const ull* wp = ((const ull*)(sm + CV_W3)) + ((ocg3 * 2 + icl) * 3 + ky) * 3;
                ull w0 = wp[0], wA = wp[1], wB = wp[2];
                #pragma unroll
                for (int x = 0; x < 5; x++) {
                    fma2(acc3p[x], w0, bc2(in[2 * x]));
                    fma2(acc3p[x], wA, bc2(in[2 * x + 1]));
                    fma2(acc3p[x], wB, bc2(in[2 * x + 2]));
                }
            }
        }
        __syncthreads();
    }

    float* outp = c3out + (long)blockIdx.x * CNN_FLAT;
    #pragma unroll
    for (int x = 0; x < 5; x++) {
        float2 f = up2(acc3p[x]);
        outp[(long)(ocg3 * 2 + 0) * 40 + y3 * 5 + x] = fmaxf(f.x, 0.f);
        outp[(long)(ocg3 * 2 + 1) * 40 + y3 * 5 + x] = fmaxf(f.y, 0.f);
    }
}

// ---------------------------------------------------------------------------
// Tiled SGEMM with f32x2 microkernel. C[M,N] = A*B^T + bias(+bias2), ReLU?
// ---------------------------------------------------------------------------
template <bool RELU, bool TO_OUT>
__global__ void __launch_bounds__(256, 2) gemm_bt_kernel(
    const void* __restrict__ Araw, long a_n,
    const float* __restrict__ Af, long lda,
    const void* __restrict__ B, long b_n,
    const void* __restrict__ bias, long bias_n,
    const void* __restrict__ bias2, long bias2_n,
    float* __restrict__ Cf, long c_off, long ldc, int N, int K,
    void* outbuf, long out_elems)
{
    __shared__ __align__(16) float sA[16][68];
    __shared__ __align__(16) float sB[16][68];

    const int tid = threadIdx.x;
    const int tx = tid & 15, ty = tid >> 4;
    const int m0 = blockIdx.x * 64;
    const int n0 = blockIdx.y * 64;
    const int bf = g_bf16;

    ull accp[4][2] = {};

    for (int k0 = 0; k0 < K; k0 += 16) {
        for (int e = tid; e < 1024; e += 256) {
            int k = e & 15, m = e >> 4;
            int gk = k0 + k;
            float v = 0.f;
            if (gk < K) {
                long ai = (long)(m0 + m) * lda + gk;
                v = Af ? Af[ai] : ldin(Araw, ai, a_n, bf);
            }
            sA[k][m] = v;
        }
        for (int e = tid; e < 1024; e += 256) {
            int k = e & 15, n = e >> 4;
            int gn = n0 + n, gk = k0 + k;
            sB[k][n] = (gn < N && gk < K) ? ldin(B, (long)gn * K + gk, b_n, bf) : 0.f;
        }
        __syncthreads();
        #pragma unroll
        for (int kk = 0; kk < 16; kk++) {
            float4 av = *(const float4*)&sA[kk][ty * 4];
            ull b0 = *(const ull*)&sB[kk][tx * 4];
            ull b1 = *(const ull*)&sB[kk][tx * 4 + 2];
            ull a0 = bc2(av.x), a1 = bc2(av.y), a2 = bc2(av.z), a3 = bc2(av.w);
            fma2(accp[0][0], a0, b0); fma2(accp[0][1], a0, b1);
            fma2(accp[1][0], a1, b0); fma2(accp[1][1], a1, b1);
            fma2(accp[2][0], a2, b0); fma2(accp[2][1], a2, b1);
            fma2(accp[3][0], a3, b0); fma2(accp[3][1], a3, b1);
        }
        __syncthreads();
    }

    #pragma unroll
    for (int i = 0; i < 4; i++) {
        int gm = m0 + ty * 4 + i;
        #pragma unroll
        for (int jp = 0; jp < 2; jp++) {
            float2 f = up2(accp[i][jp]);
            #pragma unroll
            for (int o = 0; o < 2; o++) {
                int gn = n0 + tx * 4 + jp * 2 + o;
                if (gn < N) {
                    float v = o ? f.y : f.x;
                    if (bias)  v += ldin(bias,  gn, bias_n,  bf);
                    if (bias2) v += ldin(bias2, gn, bias2_n, bf);
                    if (RELU) v = fmaxf(v, 0.f);
                    if (TO_OUT) store_out(outbuf, c_off + (long)gm * ldc + gn, out_elems, v);
                    else        Cf[(long)gm * ldc + gn] = v;
                }
            }
        }
    }
}

// ---------------------------------------------------------------------------
// LSTM (unchanged from passing R9): one CTA per batch element.
// ---------------------------------------------------------------------------
#define LW_SM_W2   0        // 22 * 512 transposed
#define LW_SM_H    11264    // 128
#define LW_SM_G    11392    // 512
#define LW_SM_TOT  11904    // 47,616 B static

__global__ void __launch_bounds__(512) lstm_kernel(
    const void* __restrict__ h0, long h0_n,
    const void* __restrict__ c0, long c0_n,
    void* outbuf, long out_elems)
{
    __shared__ float sm[LW_SM_TOT];
    float* s_w2t = sm + LW_SM_W2;
    float* s_h   = sm + LW_SM_H;
    float* s_g   = sm + LW_SM_G;

    const int b = blockIdx.x;
    const int r = threadIdx.x;
    const int bf = g_bf16;

    const float* xw   = g_sc + S_XW;
    float*       outs = g_sc + S_OUTS;

    float wreg[64];
    #pragma unroll
    for (int k = 0; k < 64; k++) wreg[k] = g_whh[r * 128 + k];
    #pragma unroll
    for (int k = 0; k < 22; k++) s_w2t[k * 512 + r] = g_whh[r * 128 + 64 + k];

    float c = 0.f;
    if (r < 128) {
        s_h[r] = ldin(h0, (long)b * 128 + r, h0_n, bf);
        c      = ldin(c0, (long)b * 128 + r, c0_n, bf);
    }
    __syncthreads();

    for (int t = 0; t < TT; t++) {
        if (r < 128) {
            float keep = (t == 0) ? 1.f : (g_done[(t - 1) * BB + b] ? 0.f : 1.f);
            s_h[r] *= keep;
            c *= keep;
        }
        __syncthreads();

        float acc = xw[((long)t * BB + b) * 512 + r];
        #pragma unroll
        for (int k = 0; k < 64; k += 4) {
            float4 h4 = *(const float4*)&s_h[k];
            acc += wreg[k] * h4.x + wreg[k + 1] * h4.y
                 + wreg[k + 2] * h4.z + wreg[k + 3] * h4.w;
        }
        #pragma unroll
        for (int k = 0; k < 22; k++)
            acc += s_w2t[k * 512 + r] * s_h[64 + k];
        const float* wg = g_whh + r * 128 + 86;
        #pragma unroll
        for (int k = 0; k < 42; k++)
            acc += wg[k] * s_h[86 + k];
        s_g[r] = acc;
        __syncthreads();

        if (r < 128) {
            float ig = 1.f / (1.f + expf(-s_g[r]));
            float fg = 1.f / (1.f + expf(-s_g[128 + r]));
            float gg = tanhf(s_g[256 + r]);
            float og = 1.f / (1.f + expf(-s_g[384 + r]));
            c = fg * c + ig * gg;
            float h = og * tanhf(c);
            s_h[r] = h;
            outs[((long)t * BB + b) * 128 + r] = h;
        }
        __syncthreads();
    }

    if (r < 128) {
        store_out(outbuf, OUT_HF + (long)b * 128 + r, out_elems, s_h[r]);
        store_out(outbuf, OUT_CF + (long)b * 128 + r, out_elems, c);
    }
}

// ---------------------------------------------------------------------------
// Value head: one warp per sample
// ---------------------------------------------------------------------------
__global__ void value_kernel(const void* __restrict__ vw, long vw_n,
                             const void* __restrict__ vb, long vb_n,
                             void* outbuf, long out_elems)
{
    int gw   = (blockIdx.x * blockDim.x + threadIdx.x) >> 5;
    int lane = threadIdx.x & 31;
    if (gw >= TB) return;
    const int bf = g_bf16;
    const float* h = g_sc + S_OUTS + (long)gw * 128;
    float s = 0.f;
    #pragma unroll
    for (int k = lane; k < 128; k += 32) s += h[k] * ldin(vw, k, vw_n, bf);
    #pragma unroll
    for (int off = 16; off; off >>= 1) s += __shfl_xor_sync(0xffffffffu, s, off);
    if (lane == 0)
        store_out(outbuf, OUT_VALUES + gw, out_elems, s + ldin(vb, 0, vb_n, bf));
}

// ---------------------------------------------------------------------------
// Host launcher — static smem only, no cudaFuncSetAttribute anywhere.
// ---------------------------------------------------------------------------
extern "C" void kernel_launch(void* const* d_in, const int* in_sizes, int n_in,
                              void* d_out, int out_size)
{
    static const long WANT[24] = {
        52559872L, 16384L, 16384L, 32768L,
        576L, 32L, 18432L, 64L, 36864L, 64L,
        327680L, 128L, 28928L, 64L, 4096L, 64L,
        98304L, 65536L, 512L, 512L,
        295040L, 2305L, 128L, 1L
    };
    const void* inp[24];
    long        bnd[24];
    {
        int matched = 0;
        static const long SCALES[3] = {1L, 4L, 2L};
        for (int si = 0; si < 3 && !matched; si++) {
            long sc = SCALES[si];
            int used[64] = {0};
            int ok = (n_in >= 24);
            const void* tp[24]; long tb[24];
            if (ok) {
                for (int j = 0; j < 24; j++) {
                    int found = -1;
                    for (int i = 0; i < n_in && i < 64; i++) {
                        if (!used[i] && (long)in_sizes[i] == WANT[j] * sc) { found = i; break; }
                    }
                    if (found < 0) { ok = 0; break; }
                    used[found] = 1;
                    tp[j] = d_in[found];
                    long actual = (long)in_sizes[found];
                    tb[j] = (WANT[j] < actual) ? WANT[j] : actual;
                }
            }
            if (ok) {
                for (int j = 0; j < 24; j++) { inp[j] = tp[j]; bnd[j] = tb[j]; }
                matched = 1;
            }
        }
        if (!matched) {
            for (int j = 0; j < 24; j++) {
                if (j < n_in) {
                    inp[j] = d_in[j];
                    long actual = (long)in_sizes[j];
                    bnd[j] = (WANT[j] < actual) ? WANT[j] : actual;
                } else {
                    inp[j] = d_in[0];
                    bnd[j] = 0;
                }
            }
        }
    }

    const long out_elems = (long)out_size;

    float *scP, *c3P;
    cudaGetSymbolAddress((void**)&scP, g_sc);
    cudaGetSymbolAddress((void**)&c3P, g_c3);

    // 1) dtype sniff + normalizers + weight prep
    detect_kernel<<<1, 256>>>(inp[0], bnd[0]);
    done_normalize_kernel<<<1, 1024>>>(inp[3], bnd[3]);
    whh_convert_kernel<<<64, 256>>>(inp[17], bnd[17]);
    weights_prep_kernel<<<64, 256>>>(
        inp[4], bnd[4], inp[5], bnd[5],
        inp[6], bnd[6], inp[7], bnd[7],
        inp[8], bnd[8], inp[9], bnd[9]);

    // 2) chunked CNN + fc GEMM -> emb cols 0..127
    for (int ch = 0; ch < NCHUNK; ch++) {
        int base = ch * CHUNK;
        conv_fused_kernel<<<CHUNK, 256>>>(inp[0], bnd[0], c3P, base);
        gemm_bt_kernel<true, false><<<dim3(CHUNK / 64, 2), 256>>>(
            nullptr, 0L, c3P, CNN_FLAT,
            inp[10], bnd[10], inp[11], bnd[11], nullptr, 0L,
            scP + S_EMB + (long)base * 192, 0L, 192, 128, CNN_FLAT,
            d_out, out_elems);
    }

    // 3) Scalar MLP -> emb cols 128..191
    gemm_bt_kernel<true, false><<<dim3(TB / 64, 1), 256>>>(
        inp[0], bnd[0], nullptr, OBS_DIM,
        inp[12], bnd[12], inp[13], bnd[13], nullptr, 0L,
        scP + S_SC1, 0L, 64, 64, SCALAR_D, d_out, out_elems);
    gemm_bt_kernel<true, false><<<dim3(TB / 64, 1), 256>>>(
        nullptr, 0L, scP + S_SC1, 64,
        inp[14], bnd[14], inp[15], bnd[15], nullptr, 0L,
        scP + S_EMB + 128, 0L, 192, 64, 64, d_out, out_elems);

    // 4) LSTM input projection
    gemm_bt_kernel<false, false><<<dim3(TB / 64, 8), 256>>>(
        nullptr, 0L, scP + S_EMB, 192,
        inp[16], bnd[16], inp[18], bnd[18], inp[19], bnd[19],
        scP + S_XW, 0L, 512, 512, 192, d_out, out_elems);

    // 5) Recurrence
    lstm_kernel<<<BB, 512>>>(inp[1], bnd[1], inp[2], bnd[2], d_out, out_elems);

    // 6) Policy head -> logits
    gemm_bt_kernel<false, true><<<dim3(TB / 64, (NACT + 63) / 64), 256>>>(
        nullptr, 0L, scP + S_OUTS, 128,
        inp[20], bnd[20], inp[21], bnd[21], nullptr, 0L,
        nullptr, OUT_LOGITS, NACT, NACT, 128, d_out, out_elems);

    // 7) Value head -> values
    value_kernel<<<TB / 8, 256>>>(inp[22], bnd[22], inp[23], bnd[23],
                                  d_out, out_elems);
}